// round 4
// baseline (speedup 1.0000x reference)
#include <cuda_runtime.h>
#include <cstdint>

#define K_DIM 8192
#define M_DIM 8192
#define N_DIM 8

// gemv tiling (unchanged from round 3)
#define ROWTILE 64
#define KC 4
#define CHUNK (K_DIM / KC)          // 2048
#define SLICE_K 64
#define NSLICES (CHUNK / SLICE_K)   // 32
#define BUF_FLOATS 4608             // W 64*64 + X 64*8
#define NBUF 3
#define SMEM_BYTES (NBUF * BUF_FLOATS * 4)   // 55296

#define SAMPLE_N (4 * 1024 * 1024)  // floats sampled for t-hat
#define BAND_CAP (2 * 1024 * 1024)  // sparse band entries (16 MB)

typedef unsigned long long ull;

// ---------------- static device scratch ----------------
__device__ float4 g_xt4[K_DIM * 2];            // x_hat transposed [K][8]
__device__ float g_ssum[256];                  // sample partials
__device__ float g_bsum[512];                  // exact |W| partials (per fused block)
__device__ float g_tlo, g_thi;                 // conservative band bounds
__device__ float g_thresh;                     // exact threshold 0.5*wdeq
__device__ float g_wdeq;
__device__ unsigned int g_bandcnt;
__device__ uint2 g_band[BAND_CAP];             // (m*8192+k, bits(w))
__device__ float g_corr[M_DIM * 8];            // correction accumulators
__device__ ull g_part[(size_t)M_DIM * KC * 4]; // f32x2 partials (1 MB)

// ---------------- helpers ----------------
__device__ __forceinline__ void fma2(ull& acc, ull x, ull q) {
    asm("fma.rn.f32x2 %0, %1, %2, %0;" : "+l"(acc) : "l"(x), "l"(q));
}
__device__ __forceinline__ void add2(ull& acc, ull x) {
    asm("add.rn.f32x2 %0, %1, %0;" : "+l"(acc) : "l"(x));
}
__device__ __forceinline__ ull qdup(float q) {
    ull q2;
    asm("mov.b64 %0, {%1, %1};" : "=l"(q2) : "f"(q));
    return q2;
}
__device__ __forceinline__ void cpasync16(void* smem_dst, const void* gsrc) {
    unsigned int sa = (unsigned int)__cvta_generic_to_shared(smem_dst);
    asm volatile("cp.async.cg.shared.global [%0], [%1], 16;" :: "r"(sa), "l"(gsrc));
}
__device__ __forceinline__ void cp_commit() { asm volatile("cp.async.commit_group;"); }
__device__ __forceinline__ void cp_wait1()  { asm volatile("cp.async.wait_group 1;"); }

__device__ __forceinline__ void push_band(bool band, int m, int k, float w, int lane) {
    unsigned mask = __ballot_sync(0xffffffffu, band);
    if (mask) {
        int ldr = __ffs(mask) - 1;
        unsigned base = 0;
        if (lane == ldr) base = atomicAdd(&g_bandcnt, (unsigned)__popc(mask));
        base = __shfl_sync(0xffffffffu, base, ldr);
        if (band) {
            unsigned pos = base + __popc(mask & ((1u << lane) - 1u));
            if (pos < BAND_CAP)
                g_band[pos] = make_uint2((unsigned)(m * K_DIM + k), __float_as_uint(w));
        }
    }
}

// ---------------- kernel 1: activation quant (+ zero corr buffer) ----------------
__global__ void quant_x_kernel(const float* __restrict__ x) {
    int gid = blockIdx.x * blockDim.x + threadIdx.x;
    g_corr[gid] = 0.f;
    g_corr[gid + 32768] = 0.f;
    int gw = gid >> 5;
    int lane = threadIdx.x & 31;
    int n = gw >> 7;
    int g = gw & 127;
    int k0 = g * 64 + lane;
    float a = x[n * K_DIM + k0];
    float b = x[n * K_DIM + k0 + 32];
    float mx = fmaxf(fabsf(a), fabsf(b));
#pragma unroll
    for (int off = 16; off; off >>= 1)
        mx = fmaxf(mx, __shfl_xor_sync(0xffffffffu, mx, off));
    float s = fmaxf(__fdiv_rn(mx, 127.0f), 1e-8f);
    float ah = rintf(__fdiv_rn(a, s)) * s;
    float bh = rintf(__fdiv_rn(b, s)) * s;
    float* xt = (float*)g_xt4;
    xt[k0 * 8 + n] = ah;
    xt[(k0 + 32) * 8 + n] = bh;
}

// ---------------- kernel 2: sampled |W| estimate (first 16 MB) ----------------
__global__ void sample_kernel(const float4* __restrict__ W4) {
    __shared__ float sm[8];
    int t0 = blockIdx.x * 256 + threadIdx.x;
    const int stride = 256 * 256;
    float s = 0.f;
#pragma unroll 4
    for (int it = 0; it < 16; it++) {
        float4 v = __ldg(W4 + t0 + (size_t)it * stride);
        s += fabsf(v.x) + fabsf(v.y) + fabsf(v.z) + fabsf(v.w);
    }
#pragma unroll
    for (int off = 16; off; off >>= 1) s += __shfl_xor_sync(0xffffffffu, s, off);
    int lane = threadIdx.x & 31, w = threadIdx.x >> 5;
    if (lane == 0) sm[w] = s;
    __syncthreads();
    if (threadIdx.x == 0) {
        float tot = 0.f;
#pragma unroll
        for (int i = 0; i < 8; i++) tot += sm[i];
        g_ssum[blockIdx.x] = tot;
    }
}

// ---------------- kernel 3: t-hat -> band bounds; reset band counter ----------------
__global__ void sample_finalize_kernel() {
    __shared__ float sm[8];
    int tid = threadIdx.x;
    float s = g_ssum[tid];
#pragma unroll
    for (int off = 16; off; off >>= 1) s += __shfl_xor_sync(0xffffffffu, s, off);
    int lane = tid & 31, w = tid >> 5;
    if (lane == 0) sm[w] = s;
    __syncthreads();
    if (tid == 0) {
        float tot = 0.f;
#pragma unroll
        for (int i = 0; i < 8; i++) tot += sm[i];
        float mean_s = tot * (1.0f / (float)SAMPLE_N);
        float t_hat = 0.5f * fmaxf(mean_s, 1e-5f);
        g_tlo = t_hat * 0.995f;
        g_thi = t_hat * 1.005f;
        g_bandcnt = 0u;
    }
}

// ---------------- kernel 4: FUSED single pass over W ----------------
// gemv with conservative threshold t_hi + exact |W| partial sums + band capture.
__global__ void __launch_bounds__(256, 4) gemv_fused_kernel(const float* __restrict__ W) {
    extern __shared__ float smem[];
    const float tlo = g_tlo, thi = g_thi;
    const int tid = threadIdx.x;
    const int lane = tid & 31, warp = tid >> 5;
    const int rt = blockIdx.x >> 2;
    const int kc = blockIdx.x & 3;
    const int rowbase = rt * ROWTILE;
    const int k0 = kc * CHUNK;
    const float* xt = (const float*)g_xt4;
    const int row_a = rowbase + lane, row_b = rowbase + lane + 32;

    auto stage = [&](int s) {
        float* buf = smem + (s % NBUF) * BUF_FLOATS;
        float* bufX = buf + ROWTILE * SLICE_K;
        int base_k = k0 + s * SLICE_K;
#pragma unroll
        for (int i = 0; i < 4; i++) {
            int idx = tid + i * 256;
            int r = idx >> 4, c = idx & 15;
            cpasync16(buf + r * SLICE_K + ((c ^ (r & 7)) << 2),
                      W + (size_t)(rowbase + r) * K_DIM + base_k + c * 4);
        }
        if (tid < 128) cpasync16(bufX + tid * 4, xt + (size_t)base_k * 8 + tid * 4);
    };

    ull a0 = 0, a1 = 0, a2 = 0, a3 = 0;
    ull b0 = 0, b1 = 0, b2 = 0, b3 = 0;
    float sabs = 0.f;

    stage(0); cp_commit();
    stage(1); cp_commit();

    const int sw = lane & 7;
    for (int s = 0; s < NSLICES; s++) {
        cp_wait1();
        __syncthreads();
        if (s + 2 < NSLICES) stage(s + 2);
        cp_commit();

        const float* buf = smem + (s % NBUF) * BUF_FLOATS;
        const ulonglong2* Xb = (const ulonglong2*)(buf + ROWTILE * SLICE_K);
        const int kbase = k0 + s * SLICE_K;
#pragma unroll
        for (int step = 0; step < 2; step++) {
            int kk = warp * 8 + step * 4;
            int ch = kk >> 2;
            float4 wa = *(const float4*)(buf + lane * SLICE_K + ((ch ^ sw) << 2));
            float4 wb = *(const float4*)(buf + (lane + 32) * SLICE_K + ((ch ^ sw) << 2));
            float wae[4] = {wa.x, wa.y, wa.z, wa.w};
            float wbe[4] = {wb.x, wb.y, wb.z, wb.w};
#pragma unroll
            for (int e = 0; e < 4; e++) {
                float va = wae[e], vb = wbe[e];
                float awa = fabsf(va), awb = fabsf(vb);
                sabs += awa;
                sabs += awb;
                bool pa = awa > thi, pb = awb > thi;
                ull qa = qdup(pa ? copysignf(1.0f, va) : 0.0f);
                ull qb = qdup(pb ? copysignf(1.0f, vb) : 0.0f);
                ulonglong2 x0 = Xb[(kk + e) * 2];
                ulonglong2 x1 = Xb[(kk + e) * 2 + 1];
                fma2(a0, x0.x, qa); fma2(a1, x0.y, qa);
                fma2(a2, x1.x, qa); fma2(a3, x1.y, qa);
                fma2(b0, x0.x, qb); fma2(b1, x0.y, qb);
                fma2(b2, x1.x, qb); fma2(b3, x1.y, qb);
                bool banda = (awa > tlo) && !pa;
                bool bandb = (awb > tlo) && !pb;
                push_band(banda, row_a, kbase + kk + e, va, lane);
                push_band(bandb, row_b, kbase + kk + e, vb, lane);
            }
        }
    }

    // ---- block reductions ----
    __syncthreads();
    // abs-sum partial (deterministic order)
#pragma unroll
    for (int off = 16; off; off >>= 1) sabs += __shfl_xor_sync(0xffffffffu, sabs, off);
    float* absm = smem + NBUF * BUF_FLOATS - 16;
    if (lane == 0) absm[warp] = sabs;

    ulonglong2* s2 = (ulonglong2*)smem;
    s2[(warp * 64 + lane) * 2]          = make_ulonglong2(a0, a1);
    s2[(warp * 64 + lane) * 2 + 1]      = make_ulonglong2(a2, a3);
    s2[(warp * 64 + lane + 32) * 2]     = make_ulonglong2(b0, b1);
    s2[(warp * 64 + lane + 32) * 2 + 1] = make_ulonglong2(b2, b3);
    __syncthreads();
    if (tid == 0) {
        float tot = 0.f;
#pragma unroll
        for (int i = 0; i < 8; i++) tot += absm[i];
        g_bsum[blockIdx.x] = tot;
    }
    if (tid < 64) {
        ull r0 = 0, r1 = 0, r2 = 0, r3 = 0;
#pragma unroll
        for (int w = 0; w < 8; w++) {
            ulonglong2 u0 = s2[(w * 64 + tid) * 2];
            ulonglong2 u1 = s2[(w * 64 + tid) * 2 + 1];
            add2(r0, u0.x); add2(r1, u0.y);
            add2(r2, u1.x); add2(r3, u1.y);
        }
        ulonglong2* P = (ulonglong2*)g_part;
        size_t p = ((size_t)(rowbase + tid) * KC + kc) * 2;
        P[p]     = make_ulonglong2(r0, r1);
        P[p + 1] = make_ulonglong2(r2, r3);
    }
}

// ---------------- kernel 5: exact mean -> threshold / wdeq ----------------
__global__ void finalize_mean_kernel() {
    __shared__ float sm[8];
    int tid = threadIdx.x;
    float s = g_bsum[tid] + g_bsum[tid + 256];
#pragma unroll
    for (int off = 16; off; off >>= 1) s += __shfl_xor_sync(0xffffffffu, s, off);
    int lane = tid & 31, w = tid >> 5;
    if (lane == 0) sm[w] = s;
    __syncthreads();
    if (tid == 0) {
        float tot = 0.f;
#pragma unroll
        for (int i = 0; i < 8; i++) tot += sm[i];
        float mean = tot * (1.0f / 67108864.0f);
        float m = fmaxf(mean, 1e-5f);
        float s_w = __fdiv_rn(1.0f, m);
        float wdeq = __fdiv_rn(1.0f, s_w);
        g_wdeq = wdeq;
        g_thresh = 0.5f * wdeq;
    }
}

// ---------------- kernel 6: replay band entries against exact threshold ----------------
__global__ void correction_kernel() {
    unsigned cnt = g_bandcnt;
    if (cnt > BAND_CAP) cnt = BAND_CAP;
    float th = g_thresh;
    for (unsigned i = blockIdx.x * 256 + threadIdx.x; i < cnt; i += 256 * 256) {
        uint2 e = g_band[i];
        float w = __uint_as_float(e.y);
        if (fabsf(w) > th) {
            float sgn = copysignf(1.0f, w);
            unsigned idx = e.x;
            int m = idx >> 13, k = idx & 8191;
            float4 x0 = g_xt4[k * 2], x1 = g_xt4[k * 2 + 1];
            float* c = g_corr + m * 8;
            atomicAdd(c + 0, sgn * x0.x);
            atomicAdd(c + 1, sgn * x0.y);
            atomicAdd(c + 2, sgn * x0.z);
            atomicAdd(c + 3, sgn * x0.w);
            atomicAdd(c + 4, sgn * x1.x);
            atomicAdd(c + 5, sgn * x1.y);
            atomicAdd(c + 6, sgn * x1.z);
            atomicAdd(c + 7, sgn * x1.w);
        }
    }
}

// ---------------- kernel 7: reduce partials + corrections, apply w_deq ----------------
__global__ void finalize_out_kernel(float* __restrict__ out) {
    int m = blockIdx.x * blockDim.x + threadIdx.x;
    const float4* p = (const float4*)g_part + (size_t)m * KC * 2;
    float s0 = 0, s1 = 0, s2 = 0, s3 = 0, s4 = 0, s5 = 0, s6 = 0, s7 = 0;
#pragma unroll
    for (int ks = 0; ks < KC; ks++) {
        float4 A = p[ks * 2];
        float4 B = p[ks * 2 + 1];
        s0 += A.x; s1 += A.y; s2 += A.z; s3 += A.w;
        s4 += B.x; s5 += B.y; s6 += B.z; s7 += B.w;
    }
    const float* c = g_corr + m * 8;
    float wd = g_wdeq;
    out[0 * M_DIM + m] = wd * (s0 + c[0]);
    out[1 * M_DIM + m] = wd * (s1 + c[1]);
    out[2 * M_DIM + m] = wd * (s2 + c[2]);
    out[3 * M_DIM + m] = wd * (s3 + c[3]);
    out[4 * M_DIM + m] = wd * (s4 + c[4]);
    out[5 * M_DIM + m] = wd * (s5 + c[5]);
    out[6 * M_DIM + m] = wd * (s6 + c[6]);
    out[7 * M_DIM + m] = wd * (s7 + c[7]);
}

// ---------------- launch ----------------
extern "C" void kernel_launch(void* const* d_in, const int* in_sizes, int n_in,
                              void* d_out, int out_size) {
    const float* x = (const float*)d_in[0];    // [8, 8192]
    const float* W = (const float*)d_in[1];    // [8192, 8192]
    float* out = (float*)d_out;                // [8, 8192]

    static bool attr_done = false;
    if (!attr_done) {
        cudaFuncSetAttribute(gemv_fused_kernel, cudaFuncAttributeMaxDynamicSharedMemorySize,
                             SMEM_BYTES);
        attr_done = true;
    }

    quant_x_kernel<<<128, 256>>>(x);                     // x_hat + zero corr
    sample_kernel<<<256, 256>>>((const float4*)W);       // 16 MB sample
    sample_finalize_kernel<<<1, 256>>>();                // t_lo / t_hi, reset counter
    gemv_fused_kernel<<<512, 256, SMEM_BYTES>>>(W);      // single 256 MB pass
    finalize_mean_kernel<<<1, 256>>>();                  // exact threshold
    correction_kernel<<<256, 256>>>();                   // band replay
    finalize_out_kernel<<<64, 128>>>(out);               // reduce + scale
}

// round 5
// speedup vs baseline: 1.8592x; 1.8592x over previous
#include <cuda_runtime.h>
#include <cstdint>

#define K_DIM 8192
#define M_DIM 8192
#define N_DIM 8

// gemv tiling
#define ROWTILE 64
#define KC 16                       // k-chunks per row (fine split for tail smoothing)
#define CHUNK (K_DIM / KC)          // 512
#define SLICE_K 64                  // k's per staged slice
#define NSLICES (CHUNK / SLICE_K)   // 8
// per buffer: W 64*64 floats (16KB) + X 64*8 floats (2KB) = 4608 floats
#define BUF_FLOATS 4608
#define NBUF 3
#define SMEM_BYTES (NBUF * BUF_FLOATS * 4)   // 55296

typedef unsigned long long ull;

// ---------------- static device scratch ----------------
__device__ float4 g_xt4[K_DIM * 2];            // x_hat transposed [K][8] (256 KB)
__device__ float g_bsum[1024];
__device__ float g_thresh;
__device__ float g_wdeq;
__device__ ull g_part[(size_t)M_DIM * KC * 4]; // 4 MB, f32x2-packed

// ---------------- helpers ----------------
__device__ __forceinline__ void fma2(ull& acc, ull x, ull q) {
    asm("fma.rn.f32x2 %0, %1, %2, %0;" : "+l"(acc) : "l"(x), "l"(q));
}
__device__ __forceinline__ void add2(ull& acc, ull x) {
    asm("add.rn.f32x2 %0, %1, %0;" : "+l"(acc) : "l"(x));
}
__device__ __forceinline__ ull qpack(float w, float t) {
    float q = (fabsf(w) > t) ? 1.0f : 0.0f;
    q = copysignf(q, w);
    ull q2;
    asm("mov.b64 %0, {%1, %1};" : "=l"(q2) : "f"(q));
    return q2;
}
__device__ __forceinline__ void cpasync16(void* smem_dst, const void* gsrc) {
    unsigned int sa = (unsigned int)__cvta_generic_to_shared(smem_dst);
    asm volatile("cp.async.cg.shared.global [%0], [%1], 16;" :: "r"(sa), "l"(gsrc));
}
__device__ __forceinline__ void cp_commit() { asm volatile("cp.async.commit_group;"); }
__device__ __forceinline__ void cp_wait1()  { asm volatile("cp.async.wait_group 1;"); }

// ---------------- kernel 1: activation per-group int8 quantization ----------------
__global__ void quant_x_kernel(const float* __restrict__ x) {
    int gw = (blockIdx.x * blockDim.x + threadIdx.x) >> 5;
    int lane = threadIdx.x & 31;
    int n = gw >> 7;
    int g = gw & 127;
    int k0 = g * 64 + lane;
    float a = x[n * K_DIM + k0];
    float b = x[n * K_DIM + k0 + 32];
    float mx = fmaxf(fabsf(a), fabsf(b));
#pragma unroll
    for (int off = 16; off; off >>= 1)
        mx = fmaxf(mx, __shfl_xor_sync(0xffffffffu, mx, off));
    float s = fmaxf(__fdiv_rn(mx, 127.0f), 1e-8f);
    float ah = rintf(__fdiv_rn(a, s)) * s;
    float bh = rintf(__fdiv_rn(b, s)) * s;
    float* xt = (float*)g_xt4;
    xt[k0 * 8 + n] = ah;
    xt[(k0 + 32) * 8 + n] = bh;
}

// ---------------- kernel 2: sum |W| — BIT-EXACT (do not touch: threshold depends on it) ----------------
__global__ void absmean_kernel(const float4* __restrict__ W4) {
    __shared__ float sm[8];
    const int stride = 1024 * 256;
    int t0 = blockIdx.x * 256 + threadIdx.x;
    const float4* p = W4 + t0;
    float s = 0.f;
#pragma unroll 2
    for (int it = 0; it < 64; it += 4) {
        float4 a = __ldg(p + (size_t)(it + 0) * stride);
        float4 b = __ldg(p + (size_t)(it + 1) * stride);
        float4 c = __ldg(p + (size_t)(it + 2) * stride);
        float4 d = __ldg(p + (size_t)(it + 3) * stride);
        s += fabsf(a.x) + fabsf(a.y) + fabsf(a.z) + fabsf(a.w);
        s += fabsf(b.x) + fabsf(b.y) + fabsf(b.z) + fabsf(b.w);
        s += fabsf(c.x) + fabsf(c.y) + fabsf(c.z) + fabsf(c.w);
        s += fabsf(d.x) + fabsf(d.y) + fabsf(d.z) + fabsf(d.w);
    }
#pragma unroll
    for (int off = 16; off; off >>= 1) s += __shfl_xor_sync(0xffffffffu, s, off);
    int lane = threadIdx.x & 31, w = threadIdx.x >> 5;
    if (lane == 0) sm[w] = s;
    __syncthreads();
    if (threadIdx.x == 0) {
        float tot = 0.f;
#pragma unroll
        for (int i = 0; i < 8; i++) tot += sm[i];
        g_bsum[blockIdx.x] = tot;
    }
}

// ---------------- kernel 3: finalize mean (bit-exact, unchanged) ----------------
__global__ void finalize_mean_kernel() {
    __shared__ float sm[8];
    int tid = threadIdx.x;
    float s = g_bsum[tid] + g_bsum[tid + 256] + g_bsum[tid + 512] + g_bsum[tid + 768];
#pragma unroll
    for (int off = 16; off; off >>= 1) s += __shfl_xor_sync(0xffffffffu, s, off);
    int lane = tid & 31, w = tid >> 5;
    if (lane == 0) sm[w] = s;
    __syncthreads();
    if (tid == 0) {
        float tot = 0.f;
#pragma unroll
        for (int i = 0; i < 8; i++) tot += sm[i];
        float mean = tot * (1.0f / 67108864.0f);
        float m = fmaxf(mean, 1e-5f);
        float s_w = __fdiv_rn(1.0f, m);
        float wdeq = __fdiv_rn(1.0f, s_w);
        g_wdeq = wdeq;
        g_thresh = 0.5f * wdeq;
    }
}

// ---------------- kernel 4: fused ternary GEMV, 3-stage cp.async pipeline ----------------
// Block: 64 rows x 512-k chunk, 8 slices of 64 k, 3 smem buffers, one barrier/slice.
// Lane owns rows (lane, lane+32); 8 warps each own an 8-k lane of every slice.
__global__ void __launch_bounds__(256, 4) gemv_kernel(const float* __restrict__ W) {
    extern __shared__ float smem[];
    const float t = g_thresh;
    const int tid = threadIdx.x;
    const int lane = tid & 31, warp = tid >> 5;
    const int rt = blockIdx.x >> 4;            // 0..127 row tiles
    const int kc = blockIdx.x & 15;            // 0..15 k chunks
    const int rowbase = rt * ROWTILE;
    const int k0 = kc * CHUNK;
    const float* xt = (const float*)g_xt4;

    auto stage = [&](int s) {
        float* buf = smem + (s % NBUF) * BUF_FLOATS;
        float* bufX = buf + ROWTILE * SLICE_K;
        int base_k = k0 + s * SLICE_K;
#pragma unroll
        for (int i = 0; i < 4; i++) {
            int idx = tid + i * 256;           // 0..1023
            int r = idx >> 4, c = idx & 15;
            cpasync16(buf + r * SLICE_K + ((c ^ (r & 7)) << 2),
                      W + (size_t)(rowbase + r) * K_DIM + base_k + c * 4);
        }
        if (tid < 128) cpasync16(bufX + tid * 4, xt + (size_t)base_k * 8 + tid * 4);
    };

    ull a0 = 0, a1 = 0, a2 = 0, a3 = 0;
    ull b0 = 0, b1 = 0, b2 = 0, b3 = 0;

    stage(0); cp_commit();
    stage(1); cp_commit();

    const int sw = lane & 7;
    for (int s = 0; s < NSLICES; s++) {
        cp_wait1();                 // slice s group complete
        __syncthreads();            // data visible; compute(s-1) done block-wide
        if (s + 2 < NSLICES) stage(s + 2);
        cp_commit();

        const float* buf = smem + (s % NBUF) * BUF_FLOATS;
        const ulonglong2* Xb = (const ulonglong2*)(buf + ROWTILE * SLICE_K);
#pragma unroll
        for (int step = 0; step < 2; step++) {
            int kk = warp * 8 + step * 4;       // slice-local k
            int ch = kk >> 2;
            float4 wa = *(const float4*)(buf + lane * SLICE_K + ((ch ^ sw) << 2));
            float4 wb = *(const float4*)(buf + (lane + 32) * SLICE_K + ((ch ^ sw) << 2));
            float wae[4] = {wa.x, wa.y, wa.z, wa.w};
            float wbe[4] = {wb.x, wb.y, wb.z, wb.w};
#pragma unroll
            for (int e = 0; e < 4; e++) {
                ulonglong2 x0 = Xb[(kk + e) * 2];
                ulonglong2 x1 = Xb[(kk + e) * 2 + 1];
                ull qa = qpack(wae[e], t);
                ull qb = qpack(wbe[e], t);
                fma2(a0, x0.x, qa); fma2(a1, x0.y, qa);
                fma2(a2, x1.x, qa); fma2(a3, x1.y, qa);
                fma2(b0, x0.x, qb); fma2(b1, x0.y, qb);
                fma2(b2, x1.x, qb); fma2(b3, x1.y, qb);
            }
        }
    }

    // ---- in-block cross-warp reduction: 8 partials/row -> 1 ----
    __syncthreads();                // all compute done; smem reusable
    ulonglong2* s2 = (ulonglong2*)smem;
    s2[(warp * 64 + lane) * 2]          = make_ulonglong2(a0, a1);
    s2[(warp * 64 + lane) * 2 + 1]      = make_ulonglong2(a2, a3);
    s2[(warp * 64 + lane + 32) * 2]     = make_ulonglong2(b0, b1);
    s2[(warp * 64 + lane + 32) * 2 + 1] = make_ulonglong2(b2, b3);
    __syncthreads();
    if (tid < 64) {
        ull r0 = 0, r1 = 0, r2 = 0, r3 = 0;
#pragma unroll
        for (int w = 0; w < 8; w++) {
            ulonglong2 u0 = s2[(w * 64 + tid) * 2];
            ulonglong2 u1 = s2[(w * 64 + tid) * 2 + 1];
            add2(r0, u0.x); add2(r1, u0.y);
            add2(r2, u1.x); add2(r3, u1.y);
        }
        ulonglong2* P = (ulonglong2*)g_part;
        size_t p = ((size_t)(rowbase + tid) * KC + kc) * 2;
        P[p]     = make_ulonglong2(r0, r1);
        P[p + 1] = make_ulonglong2(r2, r3);
    }
}

// ---------------- kernel 5: reduce KC partials, apply w_deq ----------------
__global__ void finalize_out_kernel(float* __restrict__ out) {
    int m = blockIdx.x * blockDim.x + threadIdx.x;
    const float4* p = (const float4*)g_part + (size_t)m * KC * 2;
    float s0 = 0, s1 = 0, s2 = 0, s3 = 0, s4 = 0, s5 = 0, s6 = 0, s7 = 0;
#pragma unroll
    for (int ks = 0; ks < KC; ks++) {
        float4 A = p[ks * 2];
        float4 B = p[ks * 2 + 1];
        s0 += A.x; s1 += A.y; s2 += A.z; s3 += A.w;
        s4 += B.x; s5 += B.y; s6 += B.z; s7 += B.w;
    }
    float wd = g_wdeq;
    out[0 * M_DIM + m] = wd * s0;
    out[1 * M_DIM + m] = wd * s1;
    out[2 * M_DIM + m] = wd * s2;
    out[3 * M_DIM + m] = wd * s3;
    out[4 * M_DIM + m] = wd * s4;
    out[5 * M_DIM + m] = wd * s5;
    out[6 * M_DIM + m] = wd * s6;
    out[7 * M_DIM + m] = wd * s7;
}

// ---------------- launch ----------------
extern "C" void kernel_launch(void* const* d_in, const int* in_sizes, int n_in,
                              void* d_out, int out_size) {
    const float* x = (const float*)d_in[0];    // [8, 8192]
    const float* W = (const float*)d_in[1];    // [8192, 8192]
    float* out = (float*)d_out;                // [8, 8192]

    static bool attr_done = false;
    if (!attr_done) {
        cudaFuncSetAttribute(gemv_kernel, cudaFuncAttributeMaxDynamicSharedMemorySize,
                             SMEM_BYTES);
        attr_done = true;
    }

    quant_x_kernel<<<128, 256>>>(x);
    absmean_kernel<<<1024, 256>>>((const float4*)W);
    finalize_mean_kernel<<<1, 256>>>();
    gemv_kernel<<<2048, 256, SMEM_BYTES>>>(W);
    finalize_out_kernel<<<64, 128>>>(out);
}